// round 1
// baseline (speedup 1.0000x reference)
#include <cuda_runtime.h>

// ---------------- problem constants ----------------
#define BATCH   4096
#define FRAME   267
#define LATENT  32
#define HIDDEN  256
#define GATE_H  64
#define EXPERTS 6
#define IN0     (LATENT + FRAME)    // 299
#define IN1     (LATENT + HIDDEN)   // 288
#define OUTD    FRAME               // 267

#define OFF_MU  (BATCH * OUTD)                 // 1093632
#define OFF_LV  (OFF_MU + BATCH * LATENT)      // +131072

// ---------------- scratch (allocation-free) ----------------
__device__ float g_h1[BATCH * HIDDEN];
__device__ float g_h2[BATCH * HIDDEN];
__device__ float g_zbuf[BATCH * LATENT];
__device__ float g_g1[BATCH * GATE_H];
__device__ float g_g2[BATCH * GATE_H];
__device__ float g_coef[BATCH * EXPERTS];
__device__ float g_d1[BATCH * HIDDEN];
__device__ float g_d2[BATCH * HIDDEN];

__device__ __forceinline__ float elu1(float x) { return x > 0.f ? x : expm1f(x); }

// ---------------- generic fused GEMM ----------------
// C[m,n] = act( sum_{kk<E*Din} Afold[m,kk] * W[kk,n]  + biasblend )
//   Afold[m, e*Din+i] = (i<K0 ? A0[m,i] : A1[m,i-K0]) * (coeff ? coeff[m,e] : 1)
//   biasblend = coeff ? sum_e coeff[m,e]*bias[e*N+n] : bias[n]
#define BM 64
#define BN 64
#define BK 16
#define NTHREADS 256

__global__ __launch_bounds__(NTHREADS) void gemm_fused(
    const float* __restrict__ A0, int K0, int lda0,
    const float* __restrict__ A1, int lda1,
    const float* __restrict__ coeff, int E, int Din,
    const float* __restrict__ W,
    const float* __restrict__ bias,
    float* __restrict__ C, int ldc,
    int N, int act)
{
    __shared__ float As[BK][BM + 4];
    __shared__ float Bs[BK][BN];

    const int tid = threadIdx.x;
    const int tx = tid & 15;      // 0..15  -> 4 output cols each
    const int ty = tid >> 4;      // 0..15  -> 4 output rows each
    const int bn = blockIdx.x * BN;
    const int bm = blockIdx.y * BM;
    const int Ktot = E * Din;

    // A-tile loader mapping: each thread loads 4 consecutive k for one m
    const int am  = tid >> 2;            // 0..63
    const int ak  = (tid & 3) << 2;      // 0,4,8,12
    // B-tile loader mapping: each thread loads 4 consecutive n for one k
    const int bk  = tid >> 4;            // 0..15
    const int bn0 = (tid & 15) << 2;     // 0..60

    float acc[4][4] = {};

    for (int kt = 0; kt < Ktot; kt += BK) {
        // ---- load A tile (with concat + expert-coeff folding) ----
        {
            const int m = bm + am;
            #pragma unroll
            for (int j = 0; j < 4; j++) {
                int ig = kt + ak + j;
                float v = 0.f;
                if (ig < Ktot) {
                    int e = 0, i = ig;
                    if (E > 1) { e = ig / Din; i = ig - e * Din; }
                    v = (i < K0) ? A0[m * lda0 + i] : A1[m * lda1 + (i - K0)];
                    if (coeff) v *= coeff[m * E + e];
                }
                As[ak + j][am] = v;
            }
        }
        // ---- load B (weight) tile ----
        {
            const int kg = kt + bk;
            const bool kok = (kg < Ktot);
            #pragma unroll
            for (int j = 0; j < 4; j++) {
                int n = bn + bn0 + j;
                Bs[bk][bn0 + j] = (kok && n < N) ? W[kg * N + n] : 0.f;
            }
        }
        __syncthreads();

        #pragma unroll
        for (int kk = 0; kk < BK; kk++) {
            float a[4];
            #pragma unroll
            for (int r = 0; r < 4; r++) a[r] = As[kk][(ty << 2) + r];
            float4 bv = *(const float4*)&Bs[kk][tx << 2];
            float b[4] = {bv.x, bv.y, bv.z, bv.w};
            #pragma unroll
            for (int r = 0; r < 4; r++)
                #pragma unroll
                for (int c = 0; c < 4; c++)
                    acc[r][c] = fmaf(a[r], b[c], acc[r][c]);
        }
        __syncthreads();
    }

    // ---- epilogue: bias (blended for MoE), activation, store ----
    #pragma unroll
    for (int r = 0; r < 4; r++) {
        const int m = bm + (ty << 2) + r;
        #pragma unroll
        for (int c = 0; c < 4; c++) {
            const int n = bn + (tx << 2) + c;
            if (n < N) {
                float v = acc[r][c];
                if (bias) {
                    if (coeff) {
                        float bb = 0.f;
                        for (int e = 0; e < E; e++)
                            bb = fmaf(coeff[m * E + e], bias[e * N + n], bb);
                        v += bb;
                    } else {
                        v += bias[n];
                    }
                }
                if (act == 1) v = elu1(v);
                C[m * ldc + n] = v;
            }
        }
    }
}

// ---------------- reparameterization ----------------
__global__ void z_kernel(const float* __restrict__ mu, const float* __restrict__ lv,
                         const float* __restrict__ eps, float* __restrict__ z, int n)
{
    int i = blockIdx.x * blockDim.x + threadIdx.x;
    if (i < n) z[i] = fmaf(eps[i], expf(0.5f * lv[i]), mu[i]);
}

// ---------------- final gate layer + softmax ----------------
__global__ void gate2_softmax(const float* __restrict__ gin, const float* __restrict__ w,
                              const float* __restrict__ b, float* __restrict__ coeff, int M)
{
    int n = blockIdx.x * blockDim.x + threadIdx.x;
    if (n >= M) return;
    float lg[EXPERTS];
    #pragma unroll
    for (int e = 0; e < EXPERTS; e++) lg[e] = b[e];
    const float* row = gin + n * GATE_H;
    #pragma unroll
    for (int k = 0; k < GATE_H; k++) {
        float gv = row[k];
        #pragma unroll
        for (int e = 0; e < EXPERTS; e++) lg[e] = fmaf(gv, w[k * EXPERTS + e], lg[e]);
    }
    float mx = lg[0];
    #pragma unroll
    for (int e = 1; e < EXPERTS; e++) mx = fmaxf(mx, lg[e]);
    float s = 0.f;
    #pragma unroll
    for (int e = 0; e < EXPERTS; e++) { lg[e] = expf(lg[e] - mx); s += lg[e]; }
    float inv = 1.f / s;
    #pragma unroll
    for (int e = 0; e < EXPERTS; e++) coeff[n * EXPERTS + e] = lg[e] * inv;
}

// ---------------- launch ----------------
extern "C" void kernel_launch(void* const* d_in, const int* in_sizes, int n_in,
                              void* d_out, int out_size)
{
    const float* x       = (const float*)d_in[0];
    const float* c       = (const float*)d_in[1];
    const float* eps     = (const float*)d_in[2];
    const float* enc_w1  = (const float*)d_in[3];
    const float* enc_b1  = (const float*)d_in[4];
    const float* enc_w2  = (const float*)d_in[5];
    const float* enc_b2  = (const float*)d_in[6];
    const float* enc_wmu = (const float*)d_in[7];
    const float* enc_bmu = (const float*)d_in[8];
    const float* enc_wlv = (const float*)d_in[9];
    const float* enc_blv = (const float*)d_in[10];
    const float* gw0     = (const float*)d_in[11];
    const float* gb0     = (const float*)d_in[12];
    const float* gw1     = (const float*)d_in[13];
    const float* gb1     = (const float*)d_in[14];
    const float* gw2     = (const float*)d_in[15];
    const float* gb2     = (const float*)d_in[16];
    const float* w0      = (const float*)d_in[17];
    const float* b0      = (const float*)d_in[18];
    const float* w1      = (const float*)d_in[19];
    const float* b1      = (const float*)d_in[20];
    const float* w2      = (const float*)d_in[21];
    const float* b2      = (const float*)d_in[22];
    float* out = (float*)d_out;

    float *h1, *h2, *z, *g1, *g2, *coef, *d1, *d2;
    cudaGetSymbolAddress((void**)&h1,   g_h1);
    cudaGetSymbolAddress((void**)&h2,   g_h2);
    cudaGetSymbolAddress((void**)&z,    g_zbuf);
    cudaGetSymbolAddress((void**)&g1,   g_g1);
    cudaGetSymbolAddress((void**)&g2,   g_g2);
    cudaGetSymbolAddress((void**)&coef, g_coef);
    cudaGetSymbolAddress((void**)&d1,   g_d1);
    cudaGetSymbolAddress((void**)&d2,   g_d2);

    const dim3 blk(NTHREADS);
    const dim3 gridH((HIDDEN + BN - 1) / BN, BATCH / BM);   // (4, 64)
    const dim3 grid32(1, BATCH / BM);
    const dim3 grid64(1, BATCH / BM);
    const dim3 gridO((OUTD + BN - 1) / BN, BATCH / BM);     // (5, 64)

    // encoder layer 1: h1 = elu([x, c] @ enc_w1 + b1)
    gemm_fused<<<gridH, blk>>>(x, FRAME, FRAME, c, FRAME,
                               nullptr, 1, 2 * FRAME,
                               enc_w1, enc_b1, h1, HIDDEN, HIDDEN, 1);
    // encoder layer 2: h2 = elu([x, h1] @ enc_w2 + b2)
    gemm_fused<<<gridH, blk>>>(x, FRAME, FRAME, h1, HIDDEN,
                               nullptr, 1, FRAME + HIDDEN,
                               enc_w2, enc_b2, h2, HIDDEN, HIDDEN, 1);
    // mu = [x, h2] @ enc_wmu + bmu   (written straight to output)
    gemm_fused<<<grid32, blk>>>(x, FRAME, FRAME, h2, HIDDEN,
                                nullptr, 1, FRAME + HIDDEN,
                                enc_wmu, enc_bmu, out + OFF_MU, LATENT, LATENT, 0);
    // logvar = [x, h2] @ enc_wlv + blv
    gemm_fused<<<grid32, blk>>>(x, FRAME, FRAME, h2, HIDDEN,
                                nullptr, 1, FRAME + HIDDEN,
                                enc_wlv, enc_blv, out + OFF_LV, LATENT, LATENT, 0);
    // z = mu + eps * exp(0.5*logvar)
    z_kernel<<<(BATCH * LATENT + 255) / 256, 256>>>(out + OFF_MU, out + OFF_LV, eps, z,
                                                    BATCH * LATENT);
    // gate layer 0: g1 = elu([z, c] @ gw0 + gb0)
    gemm_fused<<<grid64, blk>>>(z, LATENT, LATENT, c, FRAME,
                                nullptr, 1, IN0,
                                gw0, gb0, g1, GATE_H, GATE_H, 1);
    // gate layer 1: g2 = elu(g1 @ gw1 + gb1)
    gemm_fused<<<grid64, blk>>>(g1, GATE_H, GATE_H, g1, GATE_H,
                                nullptr, 1, GATE_H,
                                gw1, gb1, g2, GATE_H, GATE_H, 1);
    // gate layer 2 + softmax -> coeff
    gate2_softmax<<<(BATCH + 255) / 256, 256>>>(g2, gw2, gb2, coef, BATCH);

    // MoE decoder layer 0: d1 = elu( fold(coeff, [z,c]) @ w0_flat + coeff@b0 )
    gemm_fused<<<gridH, blk>>>(z, LATENT, LATENT, c, FRAME,
                               coef, EXPERTS, IN0,
                               w0, b0, d1, HIDDEN, HIDDEN, 1);
    // MoE decoder layer 1
    gemm_fused<<<gridH, blk>>>(z, LATENT, LATENT, d1, HIDDEN,
                               coef, EXPERTS, IN1,
                               w1, b1, d2, HIDDEN, HIDDEN, 1);
    // MoE decoder layer 2 (no activation) -> output "layer" region
    gemm_fused<<<gridO, blk>>>(z, LATENT, LATENT, d2, HIDDEN,
                               coef, EXPERTS, IN1,
                               w2, b2, out, OUTD, OUTD, 0);
}

// round 2
// speedup vs baseline: 2.3020x; 2.3020x over previous
#include <cuda_runtime.h>
#include <cstdint>

// ---------------- problem constants ----------------
#define BATCH   4096
#define FRAME   267
#define LATENT  32
#define HIDDEN  256
#define GATE_H  64
#define EXPERTS 6
#define IN0     (LATENT + FRAME)    // 299
#define IN1     (LATENT + HIDDEN)   // 288
#define OUTD    FRAME               // 267

#define OFF_MU  (BATCH * OUTD)
#define OFF_LV  (OFF_MU + BATCH * LATENT)

// ---------------- scratch (allocation-free) ----------------
__device__ float g_h1[BATCH * HIDDEN];
__device__ float g_h2[BATCH * HIDDEN];
__device__ float g_zbuf[BATCH * LATENT];
__device__ float g_g1[BATCH * GATE_H];
__device__ float g_g2[BATCH * GATE_H];
__device__ float g_coef[BATCH * EXPERTS];
__device__ float g_d1[BATCH * HIDDEN];
__device__ float g_d2[BATCH * HIDDEN];

__device__ __forceinline__ float elu1(float x) { return x > 0.f ? x : expm1f(x); }

__device__ __forceinline__ float tf32r(float x) {
    float y;
    asm("cvt.rna.tf32.f32 %0, %1;" : "=f"(y) : "f"(x));
    return y;
}

// ============================================================
// Tensor-core (tf32 mma.sync) fused GEMM
//   C[m,n] = act( sum_{kk} Afold[m,kk] * Wflat[kk,n] + biasblend )
//   Afold[m, e*DIN+i] = (i<K0 ? A0[m,i] : A1[m,i-K0]) * (E>1 ? coeff[m,e] : 1)
// Block tile 64x64, BK=32, 256 threads (8 warps, 4x2), warp tile 16x32.
// DUAL mode: two N=32 outputs (mu / logvar) packed into one 64-wide tile.
// ============================================================
#define BM 64
#define BN 64
#define BK 32
#define APAD 36
#define BPAD 72

template<int N_, int K0_, int DIN_, int E_, bool DUAL_, int ACT_>
__global__ __launch_bounds__(256) void mma_gemm(
    const float* __restrict__ A0, int lda0,
    const float* __restrict__ A1, int lda1,
    const float* __restrict__ coeff,
    const float* __restrict__ W,  const float* __restrict__ bias,
    const float* __restrict__ W2, const float* __restrict__ bias2,
    float* __restrict__ C, int ldc, float* __restrict__ C2)
{
    constexpr int Ktot = E_ * DIN_;
    __shared__ float As[BM][APAD];
    __shared__ float Bs[BK][BPAD];

    const int tid  = threadIdx.x;
    const int lane = tid & 31;
    const int wid  = tid >> 5;
    const int wm16 = (wid >> 1) << 4;   // warp row base (0,16,32,48)
    const int wn32 = (wid & 1) << 5;    // warp col base (0,32)
    const int gid  = lane >> 2;
    const int tg   = lane & 3;

    const int bm_ = blockIdx.y * BM;
    const int bn_ = blockIdx.x * BN;

    // loader mappings
    const int amL = tid >> 3;            // 0..31 (two halves)
    const int akq = (tid & 7) << 2;      // 0,4,...,28
    const int bkL = tid >> 4;            // 0..15 (two halves)
    const int bnb = (tid & 15) << 2;     // 0..60

    float acc[4][4] = {};

    for (int kt = 0; kt < Ktot; kt += BK) {
        // ---- A tile: concat + coeff fold + tf32 round ----
        #pragma unroll
        for (int half = 0; half < 2; half++) {
            const int mL = amL + half * 32;
            const int m  = bm_ + mL;
            float vv[4];
            #pragma unroll
            for (int j = 0; j < 4; j++) {
                const int ig = kt + akq + j;
                float val = 0.f;
                if (Ktot % BK == 0 || ig < Ktot) {
                    int e, i;
                    if (E_ == 1) { e = 0; i = ig; }
                    else { e = ig / DIN_; i = ig - e * DIN_; }
                    val = (i < K0_) ? __ldg(&A0[m * lda0 + i])
                                    : __ldg(&A1[m * lda1 + (i - K0_)]);
                    if (E_ > 1) val *= __ldg(&coeff[m * E_ + e]);
                }
                vv[j] = tf32r(val);
            }
            *(float4*)&As[mL][akq] = make_float4(vv[0], vv[1], vv[2], vv[3]);
        }
        // ---- B tile (weights) ----
        #pragma unroll
        for (int half = 0; half < 2; half++) {
            const int kL = bkL + half * 16;
            const int kg = kt + kL;
            const bool kok = (Ktot % BK == 0) || (kg < Ktot);
            float vv[4];
            #pragma unroll
            for (int j = 0; j < 4; j++) {
                float val = 0.f;
                if (kok) {
                    if (DUAL_) {
                        const int nl = bnb + j;       // bn_ == 0 in DUAL mode
                        val = (nl < 32) ? __ldg(&W [kg * 32 + nl])
                                        : __ldg(&W2[kg * 32 + (nl - 32)]);
                    } else {
                        const int n = bn_ + bnb + j;
                        if ((N_ % BN) == 0 || n < N_) val = __ldg(&W[kg * N_ + n]);
                    }
                }
                vv[j] = tf32r(val);
            }
            *(float4*)&Bs[kL][bnb] = make_float4(vv[0], vv[1], vv[2], vv[3]);
        }
        __syncthreads();

        // ---- 4 k-steps of m16n8k8 ----
        #pragma unroll
        for (int ks = 0; ks < 4; ks++) {
            const int kk = ks << 3;
            uint32_t a0 = __float_as_uint(As[wm16 + gid    ][kk + tg    ]);
            uint32_t a1 = __float_as_uint(As[wm16 + gid + 8][kk + tg    ]);
            uint32_t a2 = __float_as_uint(As[wm16 + gid    ][kk + tg + 4]);
            uint32_t a3 = __float_as_uint(As[wm16 + gid + 8][kk + tg + 4]);
            #pragma unroll
            for (int t = 0; t < 4; t++) {
                const int col = wn32 + (t << 3) + gid;
                uint32_t b0 = __float_as_uint(Bs[kk + tg    ][col]);
                uint32_t b1 = __float_as_uint(Bs[kk + tg + 4][col]);
                asm volatile(
                    "mma.sync.aligned.m16n8k8.row.col.f32.tf32.tf32.f32 "
                    "{%0,%1,%2,%3}, {%4,%5,%6,%7}, {%8,%9}, {%0,%1,%2,%3};\n"
                    : "+f"(acc[t][0]), "+f"(acc[t][1]),
                      "+f"(acc[t][2]), "+f"(acc[t][3])
                    : "r"(a0), "r"(a1), "r"(a2), "r"(a3), "r"(b0), "r"(b1));
            }
        }
        __syncthreads();
    }

    // ---- epilogue ----
    const int r0 = bm_ + wm16 + gid;
    const int r1 = r0 + 8;
    float cf0[E_ > 1 ? E_ : 1], cf1[E_ > 1 ? E_ : 1];
    if (E_ > 1) {
        #pragma unroll
        for (int e = 0; e < E_; e++) {
            cf0[e] = coeff[r0 * E_ + e];
            cf1[e] = coeff[r1 * E_ + e];
        }
    }

    #pragma unroll
    for (int t = 0; t < 4; t++) {
        #pragma unroll
        for (int q = 0; q < 4; q++) {
            const int r  = (q < 2) ? r0 : r1;
            const float* cf = (q < 2) ? cf0 : cf1;
            const int colL = wn32 + (t << 3) + (tg << 1) + (q & 1);
            float v = acc[t][q];
            if (DUAL_) {
                if (colL < 32) {
                    v += bias[colL];
                    C[r * 32 + colL] = v;
                } else {
                    v += bias2[colL - 32];
                    C2[r * 32 + (colL - 32)] = v;
                }
            } else {
                const int cG = bn_ + colL;
                if ((N_ % BN) == 0 || cG < N_) {
                    float bb;
                    if (E_ > 1) {
                        bb = 0.f;
                        #pragma unroll
                        for (int e = 0; e < E_; e++)
                            bb = fmaf(cf[e], __ldg(&bias[e * N_ + cG]), bb);
                    } else {
                        bb = bias[cG];
                    }
                    v += bb;
                    if (ACT_ == 1) v = elu1(v);
                    C[r * ldc + cG] = v;
                }
            }
        }
    }
}

// ---------------- reparameterization ----------------
__global__ void z_kernel(const float* __restrict__ mu, const float* __restrict__ lv,
                         const float* __restrict__ eps, float* __restrict__ z, int n)
{
    int i = blockIdx.x * blockDim.x + threadIdx.x;
    if (i < n) z[i] = fmaf(eps[i], expf(0.5f * lv[i]), mu[i]);
}

// ---------------- final gate layer + softmax ----------------
__global__ void gate2_softmax(const float* __restrict__ gin, const float* __restrict__ w,
                              const float* __restrict__ b, float* __restrict__ coeff, int M)
{
    int n = blockIdx.x * blockDim.x + threadIdx.x;
    if (n >= M) return;
    float lg[EXPERTS];
    #pragma unroll
    for (int e = 0; e < EXPERTS; e++) lg[e] = b[e];
    const float* row = gin + n * GATE_H;
    #pragma unroll
    for (int k = 0; k < GATE_H; k++) {
        float gv = row[k];
        #pragma unroll
        for (int e = 0; e < EXPERTS; e++) lg[e] = fmaf(gv, w[k * EXPERTS + e], lg[e]);
    }
    float mx = lg[0];
    #pragma unroll
    for (int e = 1; e < EXPERTS; e++) mx = fmaxf(mx, lg[e]);
    float s = 0.f;
    #pragma unroll
    for (int e = 0; e < EXPERTS; e++) { lg[e] = expf(lg[e] - mx); s += lg[e]; }
    float inv = 1.f / s;
    #pragma unroll
    for (int e = 0; e < EXPERTS; e++) coeff[n * EXPERTS + e] = lg[e] * inv;
}

// ---------------- launch ----------------
extern "C" void kernel_launch(void* const* d_in, const int* in_sizes, int n_in,
                              void* d_out, int out_size)
{
    const float* x       = (const float*)d_in[0];
    const float* c       = (const float*)d_in[1];
    const float* eps     = (const float*)d_in[2];
    const float* enc_w1  = (const float*)d_in[3];
    const float* enc_b1  = (const float*)d_in[4];
    const float* enc_w2  = (const float*)d_in[5];
    const float* enc_b2  = (const float*)d_in[6];
    const float* enc_wmu = (const float*)d_in[7];
    const float* enc_bmu = (const float*)d_in[8];
    const float* enc_wlv = (const float*)d_in[9];
    const float* enc_blv = (const float*)d_in[10];
    const float* gw0     = (const float*)d_in[11];
    const float* gb0     = (const float*)d_in[12];
    const float* gw1     = (const float*)d_in[13];
    const float* gb1     = (const float*)d_in[14];
    const float* gw2     = (const float*)d_in[15];
    const float* gb2     = (const float*)d_in[16];
    const float* w0      = (const float*)d_in[17];
    const float* b0      = (const float*)d_in[18];
    const float* w1      = (const float*)d_in[19];
    const float* b1      = (const float*)d_in[20];
    const float* w2      = (const float*)d_in[21];
    const float* b2      = (const float*)d_in[22];
    float* out = (float*)d_out;

    float *h1, *h2, *z, *g1, *g2, *coef, *d1, *d2;
    cudaGetSymbolAddress((void**)&h1,   g_h1);
    cudaGetSymbolAddress((void**)&h2,   g_h2);
    cudaGetSymbolAddress((void**)&z,    g_zbuf);
    cudaGetSymbolAddress((void**)&g1,   g_g1);
    cudaGetSymbolAddress((void**)&g2,   g_g2);
    cudaGetSymbolAddress((void**)&coef, g_coef);
    cudaGetSymbolAddress((void**)&d1,   g_d1);
    cudaGetSymbolAddress((void**)&d2,   g_d2);

    const dim3 blk(256);
    const dim3 gridH(HIDDEN / BN, BATCH / BM);              // (4, 64)
    const dim3 grid1(1, BATCH / BM);                        // (1, 64)
    const dim3 gridO((OUTD + BN - 1) / BN, BATCH / BM);     // (5, 64)

    // encoder layer 1: h1 = elu([x, c] @ enc_w1 + b1)   Ktot=534
    mma_gemm<HIDDEN, FRAME, 2*FRAME, 1, false, 1><<<gridH, blk>>>(
        x, FRAME, c, FRAME, nullptr, enc_w1, enc_b1, nullptr, nullptr,
        h1, HIDDEN, nullptr);
    // encoder layer 2: h2 = elu([x, h1] @ enc_w2 + b2)  Ktot=523
    mma_gemm<HIDDEN, FRAME, FRAME+HIDDEN, 1, false, 1><<<gridH, blk>>>(
        x, FRAME, h1, HIDDEN, nullptr, enc_w2, enc_b2, nullptr, nullptr,
        h2, HIDDEN, nullptr);
    // mu + logvar fused (dual 32-wide outputs)
    mma_gemm<64, FRAME, FRAME+HIDDEN, 1, true, 0><<<grid1, blk>>>(
        x, FRAME, h2, HIDDEN, nullptr, enc_wmu, enc_bmu, enc_wlv, enc_blv,
        out + OFF_MU, LATENT, out + OFF_LV);
    // z = mu + eps * exp(0.5*logvar)
    z_kernel<<<(BATCH * LATENT + 255) / 256, 256>>>(out + OFF_MU, out + OFF_LV,
                                                    eps, z, BATCH * LATENT);
    // gate layer 0: g1 = elu([z, c] @ gw0 + gb0)  Ktot=299
    mma_gemm<GATE_H, LATENT, IN0, 1, false, 1><<<grid1, blk>>>(
        z, LATENT, c, FRAME, nullptr, gw0, gb0, nullptr, nullptr,
        g1, GATE_H, nullptr);
    // gate layer 1: g2 = elu(g1 @ gw1 + gb1)  Ktot=64
    mma_gemm<GATE_H, GATE_H, GATE_H, 1, false, 1><<<grid1, blk>>>(
        g1, GATE_H, g1, GATE_H, nullptr, gw1, gb1, nullptr, nullptr,
        g2, GATE_H, nullptr);
    // gate layer 2 + softmax -> coeff
    gate2_softmax<<<(BATCH + 255) / 256, 256>>>(g2, gw2, gb2, coef, BATCH);

    // MoE decoder layer 0: Ktot = 6*299 = 1794
    mma_gemm<HIDDEN, LATENT, IN0, EXPERTS, false, 1><<<gridH, blk>>>(
        z, LATENT, c, FRAME, coef, w0, b0, nullptr, nullptr,
        d1, HIDDEN, nullptr);
    // MoE decoder layer 1: Ktot = 6*288 = 1728
    mma_gemm<HIDDEN, LATENT, IN1, EXPERTS, false, 1><<<gridH, blk>>>(
        z, LATENT, d1, HIDDEN, coef, w1, b1, nullptr, nullptr,
        d2, HIDDEN, nullptr);
    // MoE decoder layer 2 (no act): N=267, Ktot=1728
    mma_gemm<OUTD, LATENT, IN1, EXPERTS, false, 0><<<gridO, blk>>>(
        z, LATENT, d2, HIDDEN, coef, w2, b2, nullptr, nullptr,
        out, OUTD, nullptr);
}